// round 1
// baseline (speedup 1.0000x reference)
#include <cuda_runtime.h>

#define NSB   1024          // S*B
#define TLEN  640
#define DDIM  256
#define NH    64            // distinct harmonics (D / NUM_CH)
#define NWARP 8
#define NT    (TLEN / NWARP)   // 80 samples per warp

typedef unsigned long long u64;

// ---- packed fp32x2 helpers (sm_100+/sm_103a) ----
__device__ __forceinline__ u64 pk2(float lo, float hi) {
    u64 r; asm("mov.b64 %0, {%1,%2};" : "=l"(r) : "f"(lo), "f"(hi)); return r;
}
__device__ __forceinline__ void upk2(u64 v, float &lo, float &hi) {
    asm("mov.b64 {%0,%1}, %2;" : "=f"(lo), "=f"(hi) : "l"(v));
}
__device__ __forceinline__ u64 fma2(u64 a, u64 b, u64 c) {
    u64 d; asm("fma.rn.f32x2 %0, %1, %2, %3;" : "=l"(d) : "l"(a), "l"(b), "l"(c)); return d;
}
__device__ __forceinline__ u64 mul2(u64 a, u64 b) {
    u64 d; asm("mul.rn.f32x2 %0, %1, %2;" : "=l"(d) : "l"(a), "l"(b)); return d;
}

// out[sb,d] = a[d] * ( cos(phi_d)*S_h + sin(phi_d)*C_h ),  h = d>>2
//   S_h = sum_t x_t * sin(omega_h * (kT_t - tau))
//   C_h = sum_t x_t * cos(omega_h * (kT_t - tau))
// computed by a fixed-rotation recurrence per (warp t-chunk, harmonic).
__global__ __launch_bounds__(256) void sinenet_kernel(
    const float* __restrict__ x,   const float* __restrict__ nlf,
    const float* __restrict__ tau, const float* __restrict__ a,
    const float* __restrict__ phi, const float* __restrict__ i2pi,
    const float* __restrict__ kT,  float* __restrict__ out)
{
    __shared__ float  xs[TLEN];
    __shared__ float2 part[NWARP][NH];
    __shared__ float2 sums[NH];

    const int sb  = blockIdx.x;
    const int tid = threadIdx.x;
    const int w   = tid >> 5;
    const int l   = tid & 31;

    // stage x[sb, :] into shared
    const float* xb = x + sb * TLEN;
    #pragma unroll
    for (int i = tid; i < TLEN; i += 256) xs[i] = xb[i];

    // f = exp(nlf*std + mean) with mul/add rounding matching the reference
    const float nl = nlf[sb];
    const float tv = tau[sb];
    const float fF = expf(__fadd_rn(__fmul_rn(nl, 0.373288f), 5.02654f));

    const int   t0  = w * NT;
    const float tsh = __fadd_rn(kT[t0], -tv);   // k_T[t0] - tau, fp32 like reference

    // seed the two per-lane rotation chains (h = l and h = l+32) in fp64,
    // with explicit mod-2pi reduction so the float sincos sees a small arg.
    float s[2], c[2], sd[2], cd[2];
    #pragma unroll
    for (int q = 0; q < 2; ++q) {
        const int   h       = l + 32 * q;
        const float omega_f = __fmul_rn(i2pi[4 * h], fF);  // matches ref's fp32 i_f
        const double om  = (double)omega_f;
        const double th  = om * (double)tsh;
        const double dl  = om * (1.0 / 16000.0);
        const double rth = th - 6.283185307179586 * rint(th * 0.15915494309189535);
        const double rdl = dl - 6.283185307179586 * rint(dl * 0.15915494309189535);
        sincosf((float)rth, &s[q], &c[q]);
        sincosf((float)rdl, &sd[q], &cd[q]);
    }

    u64 sp  = pk2(s[0],   s[1]);
    u64 cp  = pk2(c[0],   c[1]);
    u64 sdp = pk2(sd[0],  sd[1]);
    u64 cdp = pk2(cd[0],  cd[1]);
    u64 nsd = pk2(-sd[0], -sd[1]);
    u64 Sa  = 0ull, Ca = 0ull;   // bit pattern of (0.f, 0.f)

    __syncthreads();

    // main loop: 6 packed f32x2 ops per sample covering 2 harmonics
    #pragma unroll 16
    for (int j = 0; j < NT; ++j) {
        const float xv = xs[t0 + j];          // broadcast LDS, conflict-free
        const u64   xp = pk2(xv, xv);
        Sa = fma2(xp, sp, Sa);
        Ca = fma2(xp, cp, Ca);
        const u64 t1 = mul2(cp, sdp);         // c*sd   (old c)
        const u64 t2 = mul2(sp, nsd);         // -s*sd  (old s)
        sp = fma2(sp, cdp, t1);               // s' = s*cd + c*sd
        cp = fma2(cp, cdp, t2);               // c' = c*cd - s*sd
    }

    float S0, S1, C0, C1;
    upk2(Sa, S0, S1);
    upk2(Ca, C0, C1);
    part[w][l]      = make_float2(S0, C0);
    part[w][l + 32] = make_float2(S1, C1);
    __syncthreads();

    // reduce the 8 warp partials per harmonic
    if (tid < NH) {
        float Ss = 0.f, Cs = 0.f;
        #pragma unroll
        for (int ww = 0; ww < NWARP; ++ww) {
            Ss += part[ww][tid].x;
            Cs += part[ww][tid].y;
        }
        sums[tid] = make_float2(Ss, Cs);
    }
    __syncthreads();

    // epilogue: fold phi and a per output channel
    {
        const int d = tid;
        const int h = d >> 2;
        float sph, cph;
        sincosf(phi[d], &sph, &cph);
        out[sb * DDIM + d] = a[d] * (cph * sums[h].x + sph * sums[h].y);
    }
}

extern "C" void kernel_launch(void* const* d_in, const int* in_sizes, int n_in,
                              void* d_out, int out_size)
{
    const float* x    = (const float*)d_in[0];   // (S,B,1,T)  655360
    const float* nlf  = (const float*)d_in[1];   // (S,B,1,1)  1024
    const float* tau  = (const float*)d_in[2];   // (S,B,1,1)  1024
    const float* a    = (const float*)d_in[3];   // (D,1)      256
    const float* phi  = (const float*)d_in[4];   // (D,1)      256
    const float* i2pi = (const float*)d_in[5];   // (D,1)      256
    const float* kT   = (const float*)d_in[6];   // (1,T)      640
    float* out = (float*)d_out;                  // (S,B,D)    262144

    sinenet_kernel<<<NSB, 256>>>(x, nlf, tau, a, phi, i2pi, kT, out);
}

// round 2
// speedup vs baseline: 1.6569x; 1.6569x over previous
#include <cuda_runtime.h>

#define TLEN  640
#define DDIM  256
#define NH    64            // distinct harmonics (D / NUM_CH)
#define NWARP 16
#define NT    (TLEN / NWARP)   // 40 samples per warp chunk

typedef unsigned long long u64;

// ---- packed fp32x2 helpers (sm_103a) ----
__device__ __forceinline__ u64 pk2(float lo, float hi) {
    u64 r; asm("mov.b64 %0, {%1,%2};" : "=l"(r) : "f"(lo), "f"(hi)); return r;
}
__device__ __forceinline__ void upk2(u64 v, float &lo, float &hi) {
    asm("mov.b64 {%0,%1}, %2;" : "=f"(lo), "=f"(hi) : "l"(v));
}
__device__ __forceinline__ u64 fma2(u64 a, u64 b, u64 c) {
    u64 d; asm("fma.rn.f32x2 %0, %1, %2, %3;" : "=l"(d) : "l"(a), "l"(b), "l"(c)); return d;
}

// Goertzel per (t-chunk, harmonic):  s_n = x_n + 2cos(d)*s_{n-1} - s_{n-2}
// then y = s_{N-1} - e^{-id} s_{N-2};  C + iS = e^{i psi_last} * conj(y)
//   S_h = sum_t x_t sin(w_h (kT_t - tau)),  C_h = sum_t x_t cos(...)
// out[sb,d] = a[d] * ( cos(phi_d)*S_h + sin(phi_d)*C_h ),  h = d>>2
__global__ __launch_bounds__(512) void sinenet_kernel(
    const float* __restrict__ x,   const float* __restrict__ nlf,
    const float* __restrict__ tau, const float* __restrict__ a,
    const float* __restrict__ phi, const float* __restrict__ i2pi,
    const float* __restrict__ kT,  float* __restrict__ out)
{
    __shared__ float xs[TLEN];
    __shared__ float baseHi[NWARP], baseLo[NWARP];
    __shared__ float partS[NWARP][NH], partC[NWARP][NH];
    __shared__ float sumS[NH], sumC[NH];

    const int sb  = blockIdx.x;
    const int tid = threadIdx.x;
    const int w   = tid >> 5;
    const int l   = tid & 31;

    // stage x[sb, :]
    const float* xb = x + sb * TLEN;
    #pragma unroll
    for (int i = tid; i < TLEN; i += 512) xs[i] = xb[i];

    const float nl  = nlf[sb];
    const float tv  = tau[sb];
    const float fF  = expf(__fadd_rn(__fmul_rn(nl, 0.373288f), 5.02654f));
    const float om1 = __fmul_rn(i2pi[0], fF);   // fl(2*pi*f), harmonic 1

    // one warp: fp64 base phase per t-chunk, reduced mod 2pi, split hi/lo
    if (tid < NWARP) {
        const float  tshL = __fadd_rn(kT[NT * tid + (NT - 1)], -tv);
        const double bd   = (double)om1 * (double)tshL;
        const double br   = bd - 6.283185307179586 * rint(bd * 0.15915494309189535);
        const float  hi   = (float)br;
        baseHi[tid] = hi;
        baseLo[tid] = (float)(br - (double)hi);
    }

    // per-chain seeds (pure fp32): chains h = l and h = l+32
    const float tshL = __fadd_rn(kT[w * NT + (NT - 1)], -tv);
    float cd[2], sd[2], ce[2], se[2];
    __syncthreads();   // xs + base ready
    const float bHi = baseHi[w], bLo = baseLo[w];
    #pragma unroll
    for (int q = 0; q < 2; ++q) {
        const int   h   = l + 32 * q;
        const float Hf  = (float)(h + 1);
        const float omg = __fmul_rn(i2pi[4 * h], fF);      // bit-matches reference's i_f
        const float eps = __fmaf_rn(-Hf, om1, omg);        // exact residual vs H*om1
        const float dlt = omg * (1.0f / 16000.0f);         // per-sample phase step
        const float psi = __fmaf_rn(Hf, bHi, __fmaf_rn(Hf, bLo, eps * tshL));
        sincosf(dlt, &sd[q], &cd[q]);
        sincosf(psi, &se[q], &ce[q]);
    }

    const u64 twoC = pk2(cd[0] + cd[0], cd[1] + cd[1]);
    const u64 nOne = pk2(-1.0f, -1.0f);
    u64 s1 = 0ull, s2 = 0ull;

    // main loop: 2 packed fma ops per sample covering 2 harmonics
    const int t0 = w * NT;
    #pragma unroll
    for (int j0 = 0; j0 < NT; j0 += 4) {
        const float4 xq = *reinterpret_cast<const float4*>(xs + t0 + j0);
        {   const u64 xp = pk2(xq.x, xq.x);
            const u64 tmp = fma2(nOne, s2, xp);
            const u64 ns  = fma2(twoC, s1, tmp); s2 = s1; s1 = ns; }
        {   const u64 xp = pk2(xq.y, xq.y);
            const u64 tmp = fma2(nOne, s2, xp);
            const u64 ns  = fma2(twoC, s1, tmp); s2 = s1; s1 = ns; }
        {   const u64 xp = pk2(xq.z, xq.z);
            const u64 tmp = fma2(nOne, s2, xp);
            const u64 ns  = fma2(twoC, s1, tmp); s2 = s1; s1 = ns; }
        {   const u64 xp = pk2(xq.w, xq.w);
            const u64 tmp = fma2(nOne, s2, xp);
            const u64 ns  = fma2(twoC, s1, tmp); s2 = s1; s1 = ns; }
    }

    // per-chain extraction
    float A0, A1, B0, B1;
    upk2(s1, A0, A1);
    upk2(s2, B0, B1);
    {
        const float Re = __fmaf_rn(-cd[0], B0, A0);   // s1 - cos(d)*s2
        const float Im = sd[0] * B0;                  // sin(d)*s2
        partS[w][l] = se[0] * Re - ce[0] * Im;
        partC[w][l] = ce[0] * Re + se[0] * Im;
    }
    {
        const float Re = __fmaf_rn(-cd[1], B1, A1);
        const float Im = sd[1] * B1;
        partS[w][l + 32] = se[1] * Re - ce[1] * Im;
        partC[w][l + 32] = ce[1] * Re + se[1] * Im;
    }
    __syncthreads();

    // reduce 16 chunk partials per harmonic (64 threads S, 64 threads C)
    if (tid < 128) {
        const int  h   = tid & 63;
        const bool doC = tid >= 64;
        const float (*P)[NH] = doC ? partC : partS;
        float acc = 0.0f;
        #pragma unroll
        for (int ww = 0; ww < NWARP; ++ww) acc += P[ww][h];
        if (doC) sumC[h] = acc; else sumS[h] = acc;
    }
    __syncthreads();

    // epilogue: fold phi and a per output channel
    if (tid < DDIM) {
        const int d = tid;
        const int h = d >> 2;
        float sph, cph;
        sincosf(phi[d], &sph, &cph);
        out[sb * DDIM + d] = a[d] * (cph * sumS[h] + sph * sumC[h]);
    }
}

extern "C" void kernel_launch(void* const* d_in, const int* in_sizes, int n_in,
                              void* d_out, int out_size)
{
    const float* x    = (const float*)d_in[0];   // (S,B,1,T)
    const float* nlf  = (const float*)d_in[1];   // (S,B,1,1)
    const float* tau  = (const float*)d_in[2];   // (S,B,1,1)
    const float* a    = (const float*)d_in[3];   // (D,1)
    const float* phi  = (const float*)d_in[4];   // (D,1)
    const float* i2pi = (const float*)d_in[5];   // (D,1)
    const float* kT   = (const float*)d_in[6];   // (1,T)
    float* out = (float*)d_out;                  // (S,B,D)

    sinenet_kernel<<<1024, 512>>>(x, nlf, tau, a, phi, i2pi, kT, out);
}

// round 3
// speedup vs baseline: 1.9651x; 1.1860x over previous
#include <cuda_runtime.h>

#define TLEN  640
#define DDIM  256
#define NH    64              // distinct harmonics (D / NUM_CH)
#define NWARP 8
#define NT    (TLEN / NWARP)  // 80 samples per warp chunk

typedef unsigned long long u64;

__device__ __forceinline__ u64 pk2(float lo, float hi) {
    u64 r; asm("mov.b64 %0, {%1,%2};" : "=l"(r) : "f"(lo), "f"(hi)); return r;
}
__device__ __forceinline__ void upk2(u64 v, float &lo, float &hi) {
    asm("mov.b64 {%0,%1}, %2;" : "=f"(lo), "=f"(hi) : "l"(v));
}
__device__ __forceinline__ u64 fma2(u64 a, u64 b, u64 c) {
    u64 d; asm("fma.rn.f32x2 %0, %1, %2, %3;" : "=l"(d) : "l"(a), "l"(b), "l"(c)); return d;
}

#define INV2PI 0.15915494309189535f
#define PI2_HI 6.28125f                    // 8-bit mantissa: k*PI2_HI exact for k<=32
#define PI2_LO 1.9353071795864769e-3f

// Goertzel per (t-chunk, harmonic):  s_n = x_n + 2cos(d)*s_{n-1} - s_{n-2}
// y = s_{N-1} - e^{-id} s_{N-2};  C + iS = e^{i psi_last} * conj(y)
// out[sb,d] = a[d] * ( cos(phi_d)*S_h + sin(phi_d)*C_h ),  h = d>>2
__global__ __launch_bounds__(256) void sinenet_kernel(
    const float* __restrict__ x,   const float* __restrict__ nlf,
    const float* __restrict__ tau, const float* __restrict__ a,
    const float* __restrict__ phi, const float* __restrict__ i2pi,
    const float* __restrict__ kT,  float* __restrict__ out)
{
    __shared__ __align__(16) float2 xs2[TLEN];   // x duplicated: {x,x}
    __shared__ float omgS[NH], cdS[NH], sdS[NH];
    __shared__ float baseHi[NWARP], baseLo[NWARP];
    __shared__ float partS[NWARP][NH], partC[NWARP][NH];
    __shared__ float sumS[NH], sumC[NH];

    const int sb  = blockIdx.x;
    const int tid = threadIdx.x;
    const int w   = tid >> 5;
    const int l   = tid & 31;

    // stage x[sb,:] duplicated into shared
    const float* xb = x + sb * TLEN;
    #pragma unroll
    for (int i = tid; i < TLEN; i += 256) {
        const float v = xb[i];
        xs2[i] = make_float2(v, v);
    }

    const float tv = tau[sb];

    // tid<64: per-harmonic omega + accurate sincos(delta) once per block.
    // tid<NWARP (subset): fp64 base phase of its chunk, mod 2pi, split hi/lo.
    if (tid < NH) {
        const float fF  = expf(__fadd_rn(__fmul_rn(nlf[sb], 0.373288f), 5.02654f));
        const float omg = __fmul_rn(i2pi[4 * tid], fF);   // bit-matches ref's i_f
        omgS[tid] = omg;
        sincosf(omg * (1.0f / 16000.0f), &sdS[tid], &cdS[tid]);
        if (tid < NWARP) {
            const float  om1  = __fmul_rn(i2pi[0], fF);
            const float  tshc = __fadd_rn(kT[NT * tid + (NT - 1)], -tv);
            const double bd   = (double)om1 * (double)tshc;
            const double br   = bd - 6.283185307179586 * rint(bd * 0.15915494309189535);
            const float  hi   = (float)br;
            baseHi[tid] = hi;
            baseLo[tid] = (float)(br - (double)hi);
        }
    }
    __syncthreads();

    // per-chain seeds (chains h = l and h = l+32), all fp32 fast path
    const float tshL = __fadd_rn(kT[w * NT + (NT - 1)], -tv);
    const float bHi  = baseHi[w], bLo = baseLo[w];
    const float om1  = omgS[0];
    float cd[2], sd[2], ce[2], se[2];
    #pragma unroll
    for (int q = 0; q < 2; ++q) {
        const int   h   = l + 32 * q;
        const float Hf  = (float)(h + 1);
        const float omg = omgS[h];
        cd[q] = cdS[h];  sd[q] = sdS[h];
        const float eps = __fmaf_rn(-Hf, om1, omg);          // exact residual
        // psi = Hf*(bHi+bLo) + eps*tshL, Cody-Waite reduced mod 2pi
        const float p   = Hf * bHi;
        const float pe  = __fmaf_rn(Hf, bHi, -p);            // exact low part
        const float plo = __fmaf_rn(Hf, bLo, __fmaf_rn(eps, tshL, pe));
        const float k   = rintf(p * INV2PI);
        float r = __fmaf_rn(-k, PI2_HI, p);
        r = __fmaf_rn(-k, PI2_LO, r) + plo;
        __sincosf(r, &se[q], &ce[q]);
    }

    const u64 twoC = pk2(cd[0] + cd[0], cd[1] + cd[1]);
    const u64 nOne = pk2(-1.0f, -1.0f);
    u64 s1 = 0ull, s2 = 0ull;

    // main loop: 1 LDS.128 + 4 packed fma per 2 samples (2 harmonics/thread)
    const ulonglong2* xp = reinterpret_cast<const ulonglong2*>(xs2 + w * NT);
    #pragma unroll 10
    for (int j = 0; j < NT / 2; ++j) {
        const ulonglong2 xv = xp[j];
        u64 t0 = fma2(nOne, s2, xv.x);
        u64 n0 = fma2(twoC, s1, t0);  s2 = s1; s1 = n0;
        u64 t1 = fma2(nOne, s2, xv.y);
        u64 n1 = fma2(twoC, s1, t1);  s2 = s1; s1 = n1;
    }

    // per-chain extraction
    float A0, A1, B0, B1;
    upk2(s1, A0, A1);
    upk2(s2, B0, B1);
    {
        const float Re = __fmaf_rn(-cd[0], B0, A0);
        const float Im = sd[0] * B0;
        partS[w][l] = se[0] * Re - ce[0] * Im;
        partC[w][l] = ce[0] * Re + se[0] * Im;
    }
    {
        const float Re = __fmaf_rn(-cd[1], B1, A1);
        const float Im = sd[1] * B1;
        partS[w][l + 32] = se[1] * Re - ce[1] * Im;
        partC[w][l + 32] = ce[1] * Re + se[1] * Im;
    }
    __syncthreads();

    // reduce 8 chunk partials per harmonic (64 threads S, 64 threads C)
    if (tid < 128) {
        const int  h   = tid & 63;
        const bool doC = tid >= 64;
        const float (*P)[NH] = doC ? partC : partS;
        float acc = 0.0f;
        #pragma unroll
        for (int ww = 0; ww < NWARP; ++ww) acc += P[ww][h];
        if (doC) sumC[h] = acc; else sumS[h] = acc;
    }
    __syncthreads();

    // epilogue: fold phi and a per output channel
    {
        const int d = tid;
        const int h = d >> 2;
        float sph, cph;
        __sincosf(phi[d], &sph, &cph);
        out[sb * DDIM + d] = a[d] * (cph * sumS[h] + sph * sumC[h]);
    }
}

extern "C" void kernel_launch(void* const* d_in, const int* in_sizes, int n_in,
                              void* d_out, int out_size)
{
    const float* x    = (const float*)d_in[0];   // (S,B,1,T)
    const float* nlf  = (const float*)d_in[1];   // (S,B,1,1)
    const float* tau  = (const float*)d_in[2];   // (S,B,1,1)
    const float* a    = (const float*)d_in[3];   // (D,1)
    const float* phi  = (const float*)d_in[4];   // (D,1)
    const float* i2pi = (const float*)d_in[5];   // (D,1)
    const float* kT   = (const float*)d_in[6];   // (1,T)
    float* out = (float*)d_out;                  // (S,B,D)

    sinenet_kernel<<<1024, 256>>>(x, nlf, tau, a, phi, i2pi, kT, out);
}

// round 4
// speedup vs baseline: 1.9766x; 1.0058x over previous
#include <cuda_runtime.h>

#define TLEN  640
#define DDIM  256
#define NH    64              // distinct harmonics (D / NUM_CH)
#define NWARP 8
#define NT    (TLEN / NWARP)  // 80 samples per warp chunk

typedef unsigned long long u64;

__device__ __forceinline__ u64 pk2(float lo, float hi) {
    u64 r; asm("mov.b64 %0, {%1,%2};" : "=l"(r) : "f"(lo), "f"(hi)); return r;
}
__device__ __forceinline__ void upk2(u64 v, float &lo, float &hi) {
    asm("mov.b64 {%0,%1}, %2;" : "=f"(lo), "=f"(hi) : "l"(v));
}
__device__ __forceinline__ u64 fma2(u64 a, u64 b, u64 c) {
    u64 d; asm("fma.rn.f32x2 %0, %1, %2, %3;" : "=l"(d) : "l"(a), "l"(b), "l"(c)); return d;
}

#define INV2PI 0.15915494309189535f
#define PI2_HI 6.28125f                    // 8-bit mantissa: k*PI2_HI exact for k<=32
#define PI2_LO 1.9353071795864769e-3f

// Even/odd-decimated Goertzel per (t-chunk, harmonic):
//   even samples x_{2u} and odd samples x_{2u+1} each run
//   s_n = x_n + 2cos(2d)*s_{n-1} - s_{n-2}   (40 steps, independent chains)
//   y = s_{N-1} - e^{-i2d} s_{N-2};  conj(y_tot) = e^{-id} conj(y_e) + conj(y_o)
//   C + iS = e^{i psi_last} * conj(y_tot)
// out[sb,dd] = a[dd] * ( cos(phi)*S_h + sin(phi)*C_h ),  h = dd>>2
__global__ __launch_bounds__(256, 6) void sinenet_kernel(
    const float* __restrict__ x,   const float* __restrict__ nlf,
    const float* __restrict__ tau, const float* __restrict__ a,
    const float* __restrict__ phi, const float* __restrict__ i2pi,
    const float* __restrict__ kT,  float* __restrict__ out)
{
    __shared__ __align__(16) float2 xs2[TLEN];   // x duplicated: {x,x}
    __shared__ float omgS[NH], cdS[NH], sdS[NH];
    __shared__ float baseHi[NWARP], baseLo[NWARP];
    __shared__ float partS[NWARP][NH], partC[NWARP][NH];
    __shared__ float sumS[NH], sumC[NH];

    const int sb  = blockIdx.x;
    const int tid = threadIdx.x;
    const int w   = tid >> 5;
    const int l   = tid & 31;

    // stage x[sb,:] duplicated into shared (vectorized: 160 float4 loads)
    if (tid < TLEN / 4) {
        const float4 v = reinterpret_cast<const float4*>(x + sb * TLEN)[tid];
        xs2[4 * tid + 0] = make_float2(v.x, v.x);
        xs2[4 * tid + 1] = make_float2(v.y, v.y);
        xs2[4 * tid + 2] = make_float2(v.z, v.z);
        xs2[4 * tid + 3] = make_float2(v.w, v.w);
    }

    const float tv = tau[sb];

    // tid<64: per-harmonic omega + accurate sincos(delta) once per block.
    // tid<NWARP: fp64 base phase of its chunk, mod 2pi, split hi/lo.
    if (tid < NH) {
        const float fF  = expf(__fadd_rn(__fmul_rn(nlf[sb], 0.373288f), 5.02654f));
        const float omg = __fmul_rn(i2pi[4 * tid], fF);   // bit-matches ref's i_f
        omgS[tid] = omg;
        sincosf(omg * (1.0f / 16000.0f), &sdS[tid], &cdS[tid]);
        if (tid < NWARP) {
            const float  om1  = __fmul_rn(i2pi[0], fF);
            const float  tshc = __fadd_rn(kT[NT * tid + (NT - 1)], -tv);
            const double bd   = (double)om1 * (double)tshc;
            const double br   = bd - 6.283185307179586 * rint(bd * 0.15915494309189535);
            const float  hi   = (float)br;
            baseHi[tid] = hi;
            baseLo[tid] = (float)(br - (double)hi);
        }
    }
    __syncthreads();

    // per-chain seeds (chains h = l and h = l+32), fp32 fast path
    const float tshL = __fadd_rn(kT[w * NT + (NT - 1)], -tv);
    const float bHi  = baseHi[w], bLo = baseLo[w];
    const float om1  = omgS[0];
    float cd[2], sd[2], cd2[2], sd2[2], ce[2], se[2];
    #pragma unroll
    for (int q = 0; q < 2; ++q) {
        const int   h   = l + 32 * q;
        const float Hf  = (float)(h + 1);
        const float omg = omgS[h];
        cd[q]  = cdS[h];  sd[q] = sdS[h];
        cd2[q] = __fmaf_rn(-(sd[q] + sd[q]), sd[q], 1.0f);   // cos(2d)
        sd2[q] = (cd[q] + cd[q]) * sd[q];                    // sin(2d)
        const float eps = __fmaf_rn(-Hf, om1, omg);          // exact residual
        // psi = Hf*(bHi+bLo) + eps*tshL, Cody-Waite reduced mod 2pi
        const float p   = Hf * bHi;
        const float pe  = __fmaf_rn(Hf, bHi, -p);            // exact low part
        const float plo = __fmaf_rn(Hf, bLo, __fmaf_rn(eps, tshL, pe));
        const float k   = rintf(p * INV2PI);
        float r = __fmaf_rn(-k, PI2_HI, p);
        r = __fmaf_rn(-k, PI2_LO, r) + plo;
        __sincosf(r, &se[q], &ce[q]);
    }

    const u64 twoC2 = pk2(cd2[0] + cd2[0], cd2[1] + cd2[1]);
    const u64 nOne  = pk2(-1.0f, -1.0f);
    u64 e1 = 0ull, e2 = 0ull, o1 = 0ull, o2 = 0ull;

    // main loop: 1 LDS.128 + 4 packed fma per 2 samples, 2 independent chains
    const ulonglong2* xp = reinterpret_cast<const ulonglong2*>(xs2 + w * NT);
    #pragma unroll 8
    for (int u = 0; u < NT / 2; ++u) {
        const ulonglong2 xv = xp[u];
        const u64 te = fma2(nOne, e2, xv.x);
        const u64 ne = fma2(twoC2, e1, te);
        e2 = e1; e1 = ne;
        const u64 to = fma2(nOne, o2, xv.y);
        const u64 no = fma2(twoC2, o1, to);
        o2 = o1; o1 = no;
    }

    // per-chain extraction: combine even/odd, rotate by psi_last
    float Ae[2], Be[2], Ao[2], Bo[2];
    upk2(e1, Ae[0], Ae[1]);  upk2(e2, Be[0], Be[1]);
    upk2(o1, Ao[0], Ao[1]);  upk2(o2, Bo[0], Bo[1]);
    #pragma unroll
    for (int q = 0; q < 2; ++q) {
        const float ReE = __fmaf_rn(-cd2[q], Be[q], Ae[q]);
        const float ImE = sd2[q] * Be[q];
        const float ReO = __fmaf_rn(-cd2[q], Bo[q], Ao[q]);
        const float ImO = sd2[q] * Bo[q];
        // conj(y_tot) = (ReO + ReE*cd - ImE*sd) - i (ImO + ReE*sd + ImE*cd)
        const float ReT = ReO + __fmaf_rn(ReE, cd[q], -ImE * sd[q]);
        const float ImT = ImO + __fmaf_rn(ReE, sd[q],  ImE * cd[q]);
        const int   h   = l + 32 * q;
        partS[w][h] = se[q] * ReT - ce[q] * ImT;
        partC[w][h] = ce[q] * ReT + se[q] * ImT;
    }
    __syncthreads();

    // reduce 8 chunk partials per harmonic (64 threads S, 64 threads C)
    if (tid < 128) {
        const int  h   = tid & 63;
        const bool doC = tid >= 64;
        const float (*P)[NH] = doC ? partC : partS;
        float acc = 0.0f;
        #pragma unroll
        for (int ww = 0; ww < NWARP; ++ww) acc += P[ww][h];
        if (doC) sumC[h] = acc; else sumS[h] = acc;
    }
    __syncthreads();

    // epilogue: fold phi and a per output channel
    {
        const int d = tid;
        const int h = d >> 2;
        float sph, cph;
        __sincosf(phi[d], &sph, &cph);
        out[sb * DDIM + d] = a[d] * (cph * sumS[h] + sph * sumC[h]);
    }
}

extern "C" void kernel_launch(void* const* d_in, const int* in_sizes, int n_in,
                              void* d_out, int out_size)
{
    const float* x    = (const float*)d_in[0];   // (S,B,1,T)
    const float* nlf  = (const float*)d_in[1];   // (S,B,1,1)
    const float* tau  = (const float*)d_in[2];   // (S,B,1,1)
    const float* a    = (const float*)d_in[3];   // (D,1)
    const float* phi  = (const float*)d_in[4];   // (D,1)
    const float* i2pi = (const float*)d_in[5];   // (D,1)
    const float* kT   = (const float*)d_in[6];   // (1,T)
    float* out = (float*)d_out;                  // (S,B,D)

    sinenet_kernel<<<1024, 256>>>(x, nlf, tau, a, phi, i2pi, kT, out);
}